// round 5
// baseline (speedup 1.0000x reference)
#include <cuda_runtime.h>
#include <cuda_bf16.h>
#include <math.h>

// ---------------- problem constants ----------------
#define N_NODES 50000
#define E_EDGES 300000
#define F_IN    128
#define HID     256
#define G_GRP   1000
#define NUM_GC  5
#define NH      (N_NODES * HID)          // 12,800,000

// ---------------- scratch (single static device buffer) ----------------
// layout (floats):
//   h    @ 0
//   q    @ 1*NH
//   k    @ 2*NH
//   v    @ 3*NH
//   t    @ 4*NH   (gemm scratch: t0 / t2 / gw)
//   g    @ 5*NH
//   agg  @ 6*NH
//   kvs  @ 7*NH           (256*256)
//   kssum@ 7*NH + 65536   (256)
//   scal @ +256           (16: [0]=qss, [1]=kss)
//   deg  @ +16            (N)   (becomes dinv in place)
__device__ float d_scratch[7 * (size_t)NH + 65536 + 256 + 16 + N_NODES];

// ---------------- helpers ----------------
__device__ __forceinline__ float warp_sum(float v) {
#pragma unroll
    for (int o = 16; o; o >>= 1) v += __shfl_xor_sync(0xffffffffu, v, o);
    return v;
}

// blockDim.x == 256
__device__ __forceinline__ float block_sum_256(float v, float* sh) {
    v = warp_sum(v);
    if ((threadIdx.x & 31) == 0) sh[threadIdx.x >> 5] = v;
    __syncthreads();
    if (threadIdx.x < 32) {
        float t = (threadIdx.x < 8) ? sh[threadIdx.x] : 0.f;
        t = warp_sum(t);
        if (threadIdx.x == 0) sh[8] = t;
    }
    __syncthreads();
    float r = sh[8];
    __syncthreads();
    return r;
}

// ---------------- generic zero ----------------
__global__ void zero_kernel(float* __restrict__ p, int n) {
    int i = blockIdx.x * blockDim.x + threadIdx.x;
    if (i < n) p[i] = 0.f;
}

// ---------------- tiled SGEMM: C[M,Nn] = A[M,K] @ B[K,Nn] (+bias[Nn]) ------
// BM=64, BN=64, BK=16, 256 threads, 4x4 per thread. Requires K%16==0, Nn%64==0.
__global__ void __launch_bounds__(256) sgemm_kernel(
    const float* __restrict__ A, const float* __restrict__ B,
    const float* __restrict__ bias, float* __restrict__ C,
    int M, int Nn, int K)
{
    __shared__ float As[16][64];
    __shared__ float Bs[16][64];

    const int tid = threadIdx.x;
    const int tx = tid & 15;
    const int ty = tid >> 4;
    const int row0 = blockIdx.y * 64;
    const int col0 = blockIdx.x * 64;

    const int ar  = tid >> 2;           // 0..63 (A tile row)
    const int ac4 = (tid & 3) * 4;      // 0,4,8,12 (A tile col base)
    const int br  = tid >> 4;           // 0..15 (B tile row)
    const int bc4 = (tid & 15) * 4;     // 0..60 (B tile col base)

    float acc[4][4] = {};

    for (int k0 = 0; k0 < K; k0 += 16) {
        float4 av;
        if (row0 + ar < M)
            av = *reinterpret_cast<const float4*>(&A[(size_t)(row0 + ar) * K + k0 + ac4]);
        else
            av = make_float4(0.f, 0.f, 0.f, 0.f);
        As[ac4 + 0][ar] = av.x;
        As[ac4 + 1][ar] = av.y;
        As[ac4 + 2][ar] = av.z;
        As[ac4 + 3][ar] = av.w;

        *reinterpret_cast<float4*>(&Bs[br][bc4]) =
            *reinterpret_cast<const float4*>(&B[(size_t)(k0 + br) * Nn + col0 + bc4]);
        __syncthreads();

#pragma unroll
        for (int kk = 0; kk < 16; kk++) {
            float4 a = *reinterpret_cast<const float4*>(&As[kk][ty * 4]);
            float4 b = *reinterpret_cast<const float4*>(&Bs[kk][tx * 4]);
            float ai[4] = {a.x, a.y, a.z, a.w};
            float bj[4] = {b.x, b.y, b.z, b.w};
#pragma unroll
            for (int i = 0; i < 4; i++)
#pragma unroll
                for (int j = 0; j < 4; j++)
                    acc[i][j] += ai[i] * bj[j];
        }
        __syncthreads();
    }

    float4 bb = bias ? *reinterpret_cast<const float4*>(&bias[col0 + tx * 4])
                     : make_float4(0.f, 0.f, 0.f, 0.f);
#pragma unroll
    for (int i = 0; i < 4; i++) {
        int row = row0 + ty * 4 + i;
        if (row < M) {
            float4 o = make_float4(acc[i][0] + bb.x, acc[i][1] + bb.y,
                                   acc[i][2] + bb.z, acc[i][3] + bb.w);
            *reinterpret_cast<float4*>(&C[(size_t)row * Nn + col0 + tx * 4]) = o;
        }
    }
}

// ---------------- C[256,256] += A[L,256]^T @ B[L,256], split-K via atomics --
__global__ void __launch_bounds__(256) atb_kernel(
    const float* __restrict__ A, const float* __restrict__ B,
    float* __restrict__ C, int L, int rows_per_z)
{
    __shared__ float As[32][64];
    __shared__ float Bs[32][64];

    const int tid = threadIdx.x;
    const int tx = tid & 15;
    const int ty = tid >> 4;
    const int ar0 = blockIdx.y * 64;   // C row = A column
    const int bc0 = blockIdx.x * 64;   // C col = B column
    const int lstart = blockIdx.z * rows_per_z;
    const int lend = min(L, lstart + rows_per_z);

    float acc[4][4] = {};

    for (int l0 = lstart; l0 < lend; l0 += 32) {
#pragma unroll
        for (int p = 0; p < 2; p++) {
            int id = tid + p * 256;
            int lr = id >> 4;            // 0..31
            int c4 = (id & 15) * 4;      // 0..60
            int l = l0 + lr;
            float4 av, bv;
            if (l < lend) {
                av = *reinterpret_cast<const float4*>(&A[(size_t)l * HID + ar0 + c4]);
                bv = *reinterpret_cast<const float4*>(&B[(size_t)l * HID + bc0 + c4]);
            } else {
                av = make_float4(0.f, 0.f, 0.f, 0.f);
                bv = av;
            }
            *reinterpret_cast<float4*>(&As[lr][c4]) = av;
            *reinterpret_cast<float4*>(&Bs[lr][c4]) = bv;
        }
        __syncthreads();

#pragma unroll
        for (int l = 0; l < 32; l++) {
            float4 a = *reinterpret_cast<const float4*>(&As[l][ty * 4]);
            float4 b = *reinterpret_cast<const float4*>(&Bs[l][tx * 4]);
            float ai[4] = {a.x, a.y, a.z, a.w};
            float bj[4] = {b.x, b.y, b.z, b.w};
#pragma unroll
            for (int i = 0; i < 4; i++)
#pragma unroll
                for (int j = 0; j < 4; j++)
                    acc[i][j] += ai[i] * bj[j];
        }
        __syncthreads();
    }

#pragma unroll
    for (int i = 0; i < 4; i++)
#pragma unroll
        for (int j = 0; j < 4; j++)
            atomicAdd(&C[(size_t)(ar0 + ty * 4 + i) * HID + bc0 + tx * 4 + j], acc[i][j]);
}

// ---------------- LN + relu: out = relu(LN(t)*g + b), one block per row -----
__global__ void __launch_bounds__(256) ln_relu_kernel(
    const float* __restrict__ t, const float* __restrict__ g,
    const float* __restrict__ b, float* __restrict__ out)
{
    __shared__ float sh[16];
    int row = blockIdx.x, c = threadIdx.x;
    float v = t[(size_t)row * HID + c];
    float s  = block_sum_256(v, sh);
    float s2 = block_sum_256(v * v, sh);
    float mean = s * (1.f / HID);
    float var  = s2 * (1.f / HID) - mean * mean;
    float y = (v - mean) * rsqrtf(var + 1e-5f) * g[c] + b[c];
    out[(size_t)row * HID + c] = fmaxf(y, 0.f);
}

// ---------------- sum of squares (global scalar) ----------------
__global__ void __launch_bounds__(256) sumsq_kernel(
    const float4* __restrict__ p, int n4, float* __restrict__ out)
{
    __shared__ float sh[16];
    float s = 0.f;
    for (int i = blockIdx.x * blockDim.x + threadIdx.x; i < n4;
         i += gridDim.x * blockDim.x) {
        float4 v = p[i];
        s += v.x * v.x + v.y * v.y + v.z * v.z + v.w * v.w;
    }
    float tot = block_sum_256(s, sh);
    if (threadIdx.x == 0) atomicAdd(out, tot);
}

// ---------------- column sum + sum of squares of k ----------------
__global__ void __launch_bounds__(256) colsum_sq_kernel(
    const float* __restrict__ k, float* __restrict__ colsum, float* __restrict__ ss)
{
    __shared__ float sh[16];
    int c = threadIdx.x;
    float acc = 0.f, s2 = 0.f;
    for (int r = blockIdx.x; r < N_NODES; r += gridDim.x) {
        float v = k[(size_t)r * HID + c];
        acc += v;
        s2 += v * v;
    }
    atomicAdd(&colsum[c], acc);
    float tot = block_sum_256(s2, sh);
    if (c == 0) atomicAdd(ss, tot);
}

// ---------------- scale kvs and kssum by 1/||k|| ----------------
__global__ void scale_kvs_kernel(float* __restrict__ kvs, float* __restrict__ kssum,
                                 const float* __restrict__ scal)
{
    float sk = rsqrtf(scal[1]);
    int i = blockIdx.x * blockDim.x + threadIdx.x;
    if (i < HID * HID) kvs[i] *= sk;
    if (i < HID) kssum[i] *= sk;
}

// ---------------- TransConv epilogue: attn -> residual -> LN -> relu -> l2 --
__global__ void __launch_bounds__(256) trans_epi_kernel(
    const float* __restrict__ q, const float* __restrict__ t2,
    const float* __restrict__ v, const float* __restrict__ h,
    const float* __restrict__ kssum, const float* __restrict__ scal,
    const float* __restrict__ g1, const float* __restrict__ b1,
    float* __restrict__ out_xt)
{
    __shared__ float sh[16];
    int row = blockIdx.x, c = threadIdx.x;
    size_t o = (size_t)row * HID + c;
    float rq = rsqrtf(scal[0]);
    float qv = q[o];
    float dot = block_sum_256(qv * kssum[c], sh);
    float denom = rq * dot + (float)N_NODES;
    float attn = (rq * t2[o] + (float)N_NODES * v[o]) / denom;
    float h1 = 0.5f * attn + 0.5f * h[o];
    float s  = block_sum_256(h1, sh);
    float s2 = block_sum_256(h1 * h1, sh);
    float mean = s * (1.f / HID);
    float var  = s2 * (1.f / HID) - mean * mean;
    float y = (h1 - mean) * rsqrtf(var + 1e-5f) * g1[c] + b1[c];
    y = fmaxf(y, 0.f);
    float ss = block_sum_256(y * y, sh);
    out_xt[o] = y / fmaxf(sqrtf(ss), 1e-12f);
}

// ---------------- degree / dinv ----------------
__global__ void deg_init_kernel(float* __restrict__ deg) {
    int i = blockIdx.x * blockDim.x + threadIdx.x;
    if (i < N_NODES) deg[i] = 1.f;   // self loop
}
__global__ void deg_scatter_kernel(const int* __restrict__ dst, float* __restrict__ deg) {
    int e = blockIdx.x * blockDim.x + threadIdx.x;
    if (e < E_EDGES) atomicAdd(&deg[dst[e]], 1.f);
}
__global__ void dinv_kernel(float* __restrict__ deg) {
    int i = blockIdx.x * blockDim.x + threadIdx.x;
    if (i < N_NODES) deg[i] = rsqrtf(deg[i]);   // in-place: deg -> dinv
}

// ---------------- GCN: self loop init (agg = gw * dinv^2) ----------------
__global__ void selfinit_kernel(const float4* __restrict__ gw,
                                const float* __restrict__ dinv,
                                float4* __restrict__ agg)
{
    int idx = blockIdx.x * blockDim.x + threadIdx.x;   // over N*64
    if (idx >= N_NODES * 64) return;
    int i = idx >> 6;
    float w = dinv[i];
    w *= w;
    float4 g = gw[idx];
    agg[idx] = make_float4(g.x * w, g.y * w, g.z * w, g.w * w);
}

// ---------------- GCN: edge scatter agg[dst] += gw[src]*dinv[src]*dinv[dst] -
__global__ void edge_scatter_kernel(const int* __restrict__ src, const int* __restrict__ dst,
                                    const float* __restrict__ gw, const float* __restrict__ dinv,
                                    float* __restrict__ agg)
{
    int idx = blockIdx.x * blockDim.x + threadIdx.x;   // over E*64
    if (idx >= E_EDGES * 64) return;
    int e = idx >> 6;
    int c = (idx & 63) << 2;
    int s = src[e], d = dst[e];
    float w = dinv[s] * dinv[d];
    float4 gv = *reinterpret_cast<const float4*>(&gw[(size_t)s * HID + c]);
    float* base = &agg[(size_t)d * HID + c];
    atomicAdd(base + 0, gv.x * w);
    atomicAdd(base + 1, gv.y * w);
    atomicAdd(base + 2, gv.z * w);
    atomicAdd(base + 3, gv.w * w);
}

// ---------------- GCN: bias + BN (+relu) ----------------
__global__ void bias_bn_kernel(const float4* __restrict__ agg, const float4* __restrict__ b,
                               const float4* __restrict__ mean, const float4* __restrict__ var_,
                               const float4* __restrict__ gam, const float4* __restrict__ bet,
                               float4* __restrict__ g, int relu)
{
    int idx = blockIdx.x * blockDim.x + threadIdx.x;   // over N*64
    if (idx >= N_NODES * 64) return;
    int c4 = idx & 63;
    float4 a = agg[idx], bb = b[c4], mm = mean[c4], vv = var_[c4], gg = gam[c4], be = bet[c4];
    float4 o;
    o.x = (a.x + bb.x - mm.x) * rsqrtf(vv.x + 1e-5f) * gg.x + be.x;
    o.y = (a.y + bb.y - mm.y) * rsqrtf(vv.y + 1e-5f) * gg.y + be.y;
    o.z = (a.z + bb.z - mm.z) * rsqrtf(vv.z + 1e-5f) * gg.z + be.z;
    o.w = (a.w + bb.w - mm.w) * rsqrtf(vv.w + 1e-5f) * gg.w + be.w;
    if (relu) {
        o.x = fmaxf(o.x, 0.f); o.y = fmaxf(o.y, 0.f);
        o.z = fmaxf(o.z, 0.f); o.w = fmaxf(o.w, 0.f);
    }
    g[idx] = o;
}

// ---------------- final: l2-normalize g, write out, pool by batch ----------
__global__ void __launch_bounds__(256) final_kernel(
    const float* __restrict__ g, const int* __restrict__ batch,
    float* __restrict__ out_g, float* __restrict__ out_pool)
{
    __shared__ float sh[16];
    int row = blockIdx.x, c = threadIdx.x;
    float v = g[(size_t)row * HID + c];
    float ss = block_sum_256(v * v, sh);
    float y = v / fmaxf(sqrtf(ss), 1e-12f);
    out_g[(size_t)row * HID + c] = y;
    atomicAdd(&out_pool[(size_t)batch[row] * HID + c], y);
}

// ---------------- launcher ----------------
extern "C" void kernel_launch(void* const* d_in, const int* in_sizes, int n_in,
                              void* d_out, int out_size)
{
    const float* x       = (const float*)d_in[0];
    const int*   edge    = (const int*)  d_in[1];
    const int*   batch   = (const int*)  d_in[2];
    // d_in[3] = beta (unused by the reference)
    const float* fc_W    = (const float*)d_in[4];
    const float* fc_b    = (const float*)d_in[5];
    const float* ln0_g   = (const float*)d_in[6];
    const float* ln0_b   = (const float*)d_in[7];
    const float* Wq      = (const float*)d_in[8];
    const float* bq      = (const float*)d_in[9];
    const float* Wk      = (const float*)d_in[10];
    const float* bk      = (const float*)d_in[11];
    const float* Wv      = (const float*)d_in[12];
    const float* bv      = (const float*)d_in[13];
    const float* ln1_g   = (const float*)d_in[14];
    const float* ln1_b   = (const float*)d_in[15];
    const float* gcn_W0  = (const float*)d_in[16];
    const float* gcn_b0  = (const float*)d_in[17];
    const float* gcn_W   = (const float*)d_in[18];
    const float* gcn_b   = (const float*)d_in[19];
    const float* bn_g    = (const float*)d_in[20];
    const float* bn_b    = (const float*)d_in[21];
    const float* bn_mean = (const float*)d_in[22];
    const float* bn_var  = (const float*)d_in[23];

    const int* src = edge;
    const int* dst = edge + E_EDGES;

    float* out      = (float*)d_out;
    float* out_pool = out;                               // [G, HID]
    float* out_g    = out + (size_t)G_GRP * HID;         // [N, HID]
    float* out_xt   = out_g + (size_t)N_NODES * HID;     // [N, HID]

    float* base = nullptr;
    cudaGetSymbolAddress((void**)&base, d_scratch);
    float* p_h     = base;
    float* p_q     = base + (size_t)1 * NH;
    float* p_k     = base + (size_t)2 * NH;
    float* p_v     = base + (size_t)3 * NH;
    float* p_t     = base + (size_t)4 * NH;
    float* p_g     = base + (size_t)5 * NH;
    float* p_agg   = base + (size_t)6 * NH;
    float* p_kvs   = base + (size_t)7 * NH;
    float* p_kssum = p_kvs + HID * HID;
    float* p_scal  = p_kssum + HID;
    float* p_dinv  = p_scal + 16;

    const dim3 gemm_grid(HID / 64, (N_NODES + 63) / 64);   // (4, 782)
    const int THR = 256;

    // ===== TransConv branch =====
    // t0 = x @ fc_W + fc_b ; h = relu(LN(t0))
    sgemm_kernel<<<gemm_grid, THR>>>(x, fc_W, fc_b, p_t, N_NODES, HID, F_IN);
    ln_relu_kernel<<<N_NODES, THR>>>(p_t, ln0_g, ln0_b, p_h);

    // q, k, v
    sgemm_kernel<<<gemm_grid, THR>>>(p_h, Wq, bq, p_q, N_NODES, HID, HID);
    sgemm_kernel<<<gemm_grid, THR>>>(p_h, Wk, bk, p_k, N_NODES, HID, HID);
    sgemm_kernel<<<gemm_grid, THR>>>(p_h, Wv, bv, p_v, N_NODES, HID, HID);

    // zero kvs + kssum + scalars (contiguous)
    zero_kernel<<<(HID * HID + HID + 16 + THR - 1) / THR, THR>>>(p_kvs, HID * HID + HID + 16);

    // qss, kss, ks column sums
    sumsq_kernel<<<1024, THR>>>((const float4*)p_q, NH / 4, &p_scal[0]);
    colsum_sq_kernel<<<256, THR>>>(p_k, p_kssum, &p_scal[1]);

    // kvs = k^T v (split-K atomics), then scale by 1/||k||
    {
        const int SPLITS = 64;
        const int rows_per_z = (N_NODES + SPLITS - 1) / SPLITS;
        atb_kernel<<<dim3(HID / 64, HID / 64, SPLITS), THR>>>(p_k, p_v, p_kvs, N_NODES, rows_per_z);
    }
    scale_kvs_kernel<<<(HID * HID + THR - 1) / THR, THR>>>(p_kvs, p_kssum, p_scal);

    // t2 = q @ kvs_scaled ; epilogue -> x_trans
    sgemm_kernel<<<gemm_grid, THR>>>(p_q, p_kvs, nullptr, p_t, N_NODES, HID, HID);
    trans_epi_kernel<<<N_NODES, THR>>>(p_q, p_t, p_v, p_h, p_kssum, p_scal,
                                       ln1_g, ln1_b, out_xt);

    // ===== GCN branch =====
    deg_init_kernel<<<(N_NODES + THR - 1) / THR, THR>>>(p_dinv);
    deg_scatter_kernel<<<(E_EDGES + THR - 1) / THR, THR>>>(dst, p_dinv);
    dinv_kernel<<<(N_NODES + THR - 1) / THR, THR>>>(p_dinv);

    const int ELEM4_N = N_NODES * 64;
    const int ELEM4_E = E_EDGES * 64;

    for (int i = 0; i < NUM_GC; i++) {
        const float* W  = (i == 0) ? gcn_W0 : gcn_W + (size_t)(i - 1) * HID * HID;
        const float* bb = (i == 0) ? gcn_b0 : gcn_b + (size_t)(i - 1) * HID;
        const float* gin = (i == 0) ? x : p_g;
        int K = (i == 0) ? F_IN : HID;

        sgemm_kernel<<<gemm_grid, THR>>>(gin, W, nullptr, p_t, N_NODES, HID, K);
        selfinit_kernel<<<(ELEM4_N + THR - 1) / THR, THR>>>(
            (const float4*)p_t, p_dinv, (float4*)p_agg);
        edge_scatter_kernel<<<(ELEM4_E + THR - 1) / THR, THR>>>(
            src, dst, p_t, p_dinv, p_agg);
        bias_bn_kernel<<<(ELEM4_N + THR - 1) / THR, THR>>>(
            (const float4*)p_agg, (const float4*)bb,
            (const float4*)(bn_mean + (size_t)i * HID),
            (const float4*)(bn_var  + (size_t)i * HID),
            (const float4*)(bn_g    + (size_t)i * HID),
            (const float4*)(bn_b    + (size_t)i * HID),
            (float4*)p_g, (i != NUM_GC - 1) ? 1 : 0);
    }

    // ===== outputs: xpool (zero then pool), g (normalized) =====
    zero_kernel<<<(G_GRP * HID + THR - 1) / THR, THR>>>(out_pool, G_GRP * HID);
    final_kernel<<<N_NODES, THR>>>(p_g, batch, out_g, out_pool);
}

// round 6
// speedup vs baseline: 1.4191x; 1.4191x over previous
#include <cuda_runtime.h>
#include <cuda_bf16.h>
#include <math.h>

// ---------------- problem constants ----------------
#define N_NODES 50000
#define E_EDGES 300000
#define F_IN    128
#define HID     256
#define G_GRP   1000
#define NUM_GC  5
#define NH      (N_NODES * HID)          // 12,800,000

typedef unsigned long long ull;

// ---------------- scratch (single static device buffer) ----------------
// layout (floats):
//   h    @ 0
//   q    @ 1*NH
//   k    @ 2*NH
//   v    @ 3*NH
//   t    @ 4*NH   (gemm scratch: t0 / t2 / gw)
//   aggB @ 5*NH
//   aggA @ 6*NH
//   kvs  @ 7*NH           (256*256)
//   kssum@ +65536         (256)
//   scal @ +256           (16: [0]=qss, [1]=kss)
//   dinv @ +16            (N)
//   coef @ +N             (2*5*256: s then t)
__device__ float d_scratch[7 * (size_t)NH + 65536 + 256 + 16 + N_NODES + 2 * NUM_GC * HID];

// ---------------- f32x2 helpers ----------------
__device__ __forceinline__ void ffma2(ull& d, ull a, ull b) {
    asm("fma.rn.f32x2 %0, %1, %2, %0;" : "+l"(d) : "l"(a), "l"(b));
}
__device__ __forceinline__ ull pack2(float x, float y) {
    ull r;
    asm("mov.b64 %0, {%1, %2};" : "=l"(r) : "f"(x), "f"(y));
    return r;
}
__device__ __forceinline__ void unpack2(float& lo, float& hi, ull v) {
    asm("mov.b64 {%0, %1}, %2;" : "=f"(lo), "=f"(hi) : "l"(v));
}

// ---------------- misc helpers ----------------
__device__ __forceinline__ float warp_sum(float v) {
#pragma unroll
    for (int o = 16; o; o >>= 1) v += __shfl_xor_sync(0xffffffffu, v, o);
    return v;
}

__device__ __forceinline__ float block_sum_256(float v, float* sh) {
    v = warp_sum(v);
    if ((threadIdx.x & 31) == 0) sh[threadIdx.x >> 5] = v;
    __syncthreads();
    if (threadIdx.x < 32) {
        float t = (threadIdx.x < 8) ? sh[threadIdx.x] : 0.f;
        t = warp_sum(t);
        if (threadIdx.x == 0) sh[8] = t;
    }
    __syncthreads();
    float r = sh[8];
    __syncthreads();
    return r;
}

__global__ void zero_kernel(float* __restrict__ p, int n) {
    int i = blockIdx.x * blockDim.x + threadIdx.x;
    if (i < n) p[i] = 0.f;
}

// ============ 128x128x8 SGEMM with packed f32x2 FFMA2 ============
// C[M,Nn] = op(A)[M,K] @ B[K,Nn] (+bias), 256 threads, 8x8 per thread.
// op(A): optional per-column affine (+relu): a' = relu?(a*s[k] + t[k]).
// Optional second output C2 = C * dinv[row]^2 (GCN self-loop init).
// Requires Nn % 128 == 0, K % 8 == 0.
__global__ void __launch_bounds__(256, 2) sgemm128(
    const float* __restrict__ A, const float* __restrict__ B,
    const float* __restrict__ bias,
    const float* __restrict__ aff_s, const float* __restrict__ aff_t, int do_relu,
    float* __restrict__ C, float* __restrict__ C2, const float* __restrict__ dinv,
    int M, int Nn, int K)
{
    __shared__ __align__(16) float As[2][8][128];
    __shared__ __align__(16) float Bs[2][8][128];

    const int tid = threadIdx.x;
    const int tx = tid & 15;          // 16 col groups
    const int ty = tid >> 4;          // 16 row groups
    const int row0 = blockIdx.y * 128;
    const int col0 = blockIdx.x * 128;

    // A load: each thread one float4: row = tid>>1 (0..127), kseg = (tid&1)*4
    const int arow = tid >> 1, ak4 = (tid & 1) * 4;
    // B load: each thread one float4: krow = tid>>5 (0..7), col = (tid&31)*4
    const int brow = tid >> 5, bc4 = (tid & 31) * 4;

    const int KT = K >> 3;

    ull acc[8][4];
#pragma unroll
    for (int i = 0; i < 8; i++)
#pragma unroll
        for (int j = 0; j < 4; j++) acc[i][j] = 0ull;

    float4 av, bv;

    // ---- prologue fetch (k0 = 0) ----
    {
        int r = row0 + arow;
        if (r < M) av = *reinterpret_cast<const float4*>(&A[(size_t)r * K + ak4]);
        else       av = make_float4(0.f, 0.f, 0.f, 0.f);
        if (aff_s) {
            float4 s4 = *reinterpret_cast<const float4*>(&aff_s[ak4]);
            float4 t4 = *reinterpret_cast<const float4*>(&aff_t[ak4]);
            av.x = fmaf(av.x, s4.x, t4.x); av.y = fmaf(av.y, s4.y, t4.y);
            av.z = fmaf(av.z, s4.z, t4.z); av.w = fmaf(av.w, s4.w, t4.w);
            if (do_relu) {
                av.x = fmaxf(av.x, 0.f); av.y = fmaxf(av.y, 0.f);
                av.z = fmaxf(av.z, 0.f); av.w = fmaxf(av.w, 0.f);
            }
        }
        bv = *reinterpret_cast<const float4*>(&B[(size_t)brow * Nn + col0 + bc4]);
        As[0][ak4 + 0][arow] = av.x; As[0][ak4 + 1][arow] = av.y;
        As[0][ak4 + 2][arow] = av.z; As[0][ak4 + 3][arow] = av.w;
        *reinterpret_cast<float4*>(&Bs[0][brow][bc4]) = bv;
    }
    __syncthreads();

    for (int kt = 0; kt < KT; kt++) {
        const int buf = kt & 1;
        if (kt + 1 < KT) {
            const int k0 = (kt + 1) << 3;
            int r = row0 + arow;
            if (r < M) av = *reinterpret_cast<const float4*>(&A[(size_t)r * K + k0 + ak4]);
            else       av = make_float4(0.f, 0.f, 0.f, 0.f);
            if (aff_s) {
                float4 s4 = *reinterpret_cast<const float4*>(&aff_s[k0 + ak4]);
                float4 t4 = *reinterpret_cast<const float4*>(&aff_t[k0 + ak4]);
                av.x = fmaf(av.x, s4.x, t4.x); av.y = fmaf(av.y, s4.y, t4.y);
                av.z = fmaf(av.z, s4.z, t4.z); av.w = fmaf(av.w, s4.w, t4.w);
                if (do_relu) {
                    av.x = fmaxf(av.x, 0.f); av.y = fmaxf(av.y, 0.f);
                    av.z = fmaxf(av.z, 0.f); av.w = fmaxf(av.w, 0.f);
                }
            }
            bv = *reinterpret_cast<const float4*>(&B[(size_t)(k0 + brow) * Nn + col0 + bc4]);
        }

#pragma unroll
        for (int k = 0; k < 8; k++) {
            // a rows: ty*4 .. +3 and 64+ty*4 .. +3 (conflict-free column split)
            float4 a0 = *reinterpret_cast<const float4*>(&As[buf][k][ty * 4]);
            float4 a1 = *reinterpret_cast<const float4*>(&As[buf][k][64 + ty * 4]);
            // b cols: tx*4 .. +3 and 64+tx*4 .. +3, loaded pre-packed as f32x2 pairs
            ulonglong2 b0 = *reinterpret_cast<const ulonglong2*>(&Bs[buf][k][tx * 4]);
            ulonglong2 b1 = *reinterpret_cast<const ulonglong2*>(&Bs[buf][k][64 + tx * 4]);
            ull bp0 = b0.x, bp1 = b0.y, bp2 = b1.x, bp3 = b1.y;
            float aa[8] = {a0.x, a0.y, a0.z, a0.w, a1.x, a1.y, a1.z, a1.w};
#pragma unroll
            for (int i = 0; i < 8; i++) {
                ull ap = pack2(aa[i], aa[i]);
                ffma2(acc[i][0], ap, bp0);
                ffma2(acc[i][1], ap, bp1);
                ffma2(acc[i][2], ap, bp2);
                ffma2(acc[i][3], ap, bp3);
            }
        }

        if (kt + 1 < KT) {
            const int nb = buf ^ 1;
            As[nb][ak4 + 0][arow] = av.x; As[nb][ak4 + 1][arow] = av.y;
            As[nb][ak4 + 2][arow] = av.z; As[nb][ak4 + 3][arow] = av.w;
            *reinterpret_cast<float4*>(&Bs[nb][brow][bc4]) = bv;
        }
        __syncthreads();
    }

    // ---- epilogue ----
    float4 b_lo = make_float4(0.f, 0.f, 0.f, 0.f), b_hi = b_lo;
    if (bias) {
        b_lo = *reinterpret_cast<const float4*>(&bias[col0 + tx * 4]);
        b_hi = *reinterpret_cast<const float4*>(&bias[col0 + 64 + tx * 4]);
    }
#pragma unroll
    for (int i = 0; i < 8; i++) {
        int row = row0 + ((i < 4) ? (ty * 4 + i) : (64 + ty * 4 + (i - 4)));
        if (row >= M) continue;
        float o0, o1, o2, o3, o4, o5, o6, o7;
        unpack2(o0, o1, acc[i][0]); unpack2(o2, o3, acc[i][1]);
        unpack2(o4, o5, acc[i][2]); unpack2(o6, o7, acc[i][3]);
        float4 lo = make_float4(o0 + b_lo.x, o1 + b_lo.y, o2 + b_lo.z, o3 + b_lo.w);
        float4 hi = make_float4(o4 + b_hi.x, o5 + b_hi.y, o6 + b_hi.z, o7 + b_hi.w);
        *reinterpret_cast<float4*>(&C[(size_t)row * Nn + col0 + tx * 4]) = lo;
        *reinterpret_cast<float4*>(&C[(size_t)row * Nn + col0 + 64 + tx * 4]) = hi;
        if (C2) {
            float w = dinv[row]; w *= w;
            float4 l2v = make_float4(lo.x * w, lo.y * w, lo.z * w, lo.w * w);
            float4 h2v = make_float4(hi.x * w, hi.y * w, hi.z * w, hi.w * w);
            *reinterpret_cast<float4*>(&C2[(size_t)row * Nn + col0 + tx * 4]) = l2v;
            *reinterpret_cast<float4*>(&C2[(size_t)row * Nn + col0 + 64 + tx * 4]) = h2v;
        }
    }
}

// ---------------- C[256,256] += A[L,256]^T @ B[L,256], split-K via atomics --
__global__ void __launch_bounds__(256) atb_kernel(
    const float* __restrict__ A, const float* __restrict__ B,
    float* __restrict__ C, int L, int rows_per_z)
{
    __shared__ float As[32][64];
    __shared__ float Bs[32][64];

    const int tid = threadIdx.x;
    const int tx = tid & 15;
    const int ty = tid >> 4;
    const int ar0 = blockIdx.y * 64;
    const int bc0 = blockIdx.x * 64;
    const int lstart = blockIdx.z * rows_per_z;
    const int lend = min(L, lstart + rows_per_z);

    float acc[4][4] = {};

    for (int l0 = lstart; l0 < lend; l0 += 32) {
#pragma unroll
        for (int p = 0; p < 2; p++) {
            int id = tid + p * 256;
            int lr = id >> 4;
            int c4 = (id & 15) * 4;
            int l = l0 + lr;
            float4 avv, bvv;
            if (l < lend) {
                avv = *reinterpret_cast<const float4*>(&A[(size_t)l * HID + ar0 + c4]);
                bvv = *reinterpret_cast<const float4*>(&B[(size_t)l * HID + bc0 + c4]);
            } else {
                avv = make_float4(0.f, 0.f, 0.f, 0.f);
                bvv = avv;
            }
            *reinterpret_cast<float4*>(&As[lr][c4]) = avv;
            *reinterpret_cast<float4*>(&Bs[lr][c4]) = bvv;
        }
        __syncthreads();

#pragma unroll
        for (int l = 0; l < 32; l++) {
            float4 a = *reinterpret_cast<const float4*>(&As[l][ty * 4]);
            float4 b = *reinterpret_cast<const float4*>(&Bs[l][tx * 4]);
            float ai[4] = {a.x, a.y, a.z, a.w};
            float bj[4] = {b.x, b.y, b.z, b.w};
#pragma unroll
            for (int i = 0; i < 4; i++)
#pragma unroll
                for (int j = 0; j < 4; j++)
                    acc[i][j] += ai[i] * bj[j];
        }
        __syncthreads();
    }

#pragma unroll
    for (int i = 0; i < 4; i++)
#pragma unroll
        for (int j = 0; j < 4; j++)
            atomicAdd(&C[(size_t)(ar0 + ty * 4 + i) * HID + bc0 + tx * 4 + j], acc[i][j]);
}

// ---------------- LN + relu ----------------
__global__ void __launch_bounds__(256) ln_relu_kernel(
    const float* __restrict__ t, const float* __restrict__ g,
    const float* __restrict__ b, float* __restrict__ out)
{
    __shared__ float sh[16];
    int row = blockIdx.x, c = threadIdx.x;
    float v = t[(size_t)row * HID + c];
    float s  = block_sum_256(v, sh);
    float s2 = block_sum_256(v * v, sh);
    float mean = s * (1.f / HID);
    float var  = s2 * (1.f / HID) - mean * mean;
    float y = (v - mean) * rsqrtf(var + 1e-5f) * g[c] + b[c];
    out[(size_t)row * HID + c] = fmaxf(y, 0.f);
}

// ---------------- sum of squares ----------------
__global__ void __launch_bounds__(256) sumsq_kernel(
    const float4* __restrict__ p, int n4, float* __restrict__ out)
{
    __shared__ float sh[16];
    float s = 0.f;
    for (int i = blockIdx.x * blockDim.x + threadIdx.x; i < n4;
         i += gridDim.x * blockDim.x) {
        float4 v = p[i];
        s += v.x * v.x + v.y * v.y + v.z * v.z + v.w * v.w;
    }
    float tot = block_sum_256(s, sh);
    if (threadIdx.x == 0) atomicAdd(out, tot);
}

// ---------------- column sum + sum of squares of k ----------------
__global__ void __launch_bounds__(256) colsum_sq_kernel(
    const float* __restrict__ k, float* __restrict__ colsum, float* __restrict__ ss)
{
    __shared__ float sh[16];
    int c = threadIdx.x;
    float acc = 0.f, s2 = 0.f;
    for (int r = blockIdx.x; r < N_NODES; r += gridDim.x) {
        float v = k[(size_t)r * HID + c];
        acc += v;
        s2 += v * v;
    }
    atomicAdd(&colsum[c], acc);
    float tot = block_sum_256(s2, sh);
    if (c == 0) atomicAdd(ss, tot);
}

// ---------------- scale kvs and kssum by 1/||k|| ----------------
__global__ void scale_kvs_kernel(float* __restrict__ kvs, float* __restrict__ kssum,
                                 const float* __restrict__ scal)
{
    float sk = rsqrtf(scal[1]);
    int i = blockIdx.x * blockDim.x + threadIdx.x;
    if (i < HID * HID) kvs[i] *= sk;
    if (i < HID) kssum[i] *= sk;
}

// ---------------- TransConv epilogue ----------------
__global__ void __launch_bounds__(256) trans_epi_kernel(
    const float* __restrict__ q, const float* __restrict__ t2,
    const float* __restrict__ v, const float* __restrict__ h,
    const float* __restrict__ kssum, const float* __restrict__ scal,
    const float* __restrict__ g1, const float* __restrict__ b1,
    float* __restrict__ out_xt)
{
    __shared__ float sh[16];
    int row = blockIdx.x, c = threadIdx.x;
    size_t o = (size_t)row * HID + c;
    float rq = rsqrtf(scal[0]);
    float qv = q[o];
    float dot = block_sum_256(qv * kssum[c], sh);
    float denom = rq * dot + (float)N_NODES;
    float attn = (rq * t2[o] + (float)N_NODES * v[o]) / denom;
    float h1 = 0.5f * attn + 0.5f * h[o];
    float s  = block_sum_256(h1, sh);
    float s2 = block_sum_256(h1 * h1, sh);
    float mean = s * (1.f / HID);
    float var  = s2 * (1.f / HID) - mean * mean;
    float y = (h1 - mean) * rsqrtf(var + 1e-5f) * g1[c] + b1[c];
    y = fmaxf(y, 0.f);
    float ss = block_sum_256(y * y, sh);
    out_xt[o] = y / fmaxf(sqrtf(ss), 1e-12f);
}

// ---------------- degree / dinv ----------------
__global__ void deg_init_kernel(float* __restrict__ deg) {
    int i = blockIdx.x * blockDim.x + threadIdx.x;
    if (i < N_NODES) deg[i] = 1.f;
}
__global__ void deg_scatter_kernel(const int* __restrict__ dst, float* __restrict__ deg) {
    int e = blockIdx.x * blockDim.x + threadIdx.x;
    if (e < E_EDGES) atomicAdd(&deg[dst[e]], 1.f);
}
__global__ void dinv_kernel(float* __restrict__ deg) {
    int i = blockIdx.x * blockDim.x + threadIdx.x;
    if (i < N_NODES) deg[i] = rsqrtf(deg[i]);
}

// ---------------- BN affine coefficients (5 layers x 256) ----------------
__global__ void bn_coef_kernel(const float* __restrict__ gcn_b0, const float* __restrict__ gcn_b,
                               const float* __restrict__ bn_g, const float* __restrict__ bn_b,
                               const float* __restrict__ bn_mean, const float* __restrict__ bn_var,
                               float* __restrict__ coef_s, float* __restrict__ coef_t)
{
    int idx = blockIdx.x * blockDim.x + threadIdx.x;
    if (idx >= NUM_GC * HID) return;
    int layer = idx >> 8, c = idx & 255;
    float b = (layer == 0) ? gcn_b0[c] : gcn_b[(size_t)(layer - 1) * HID + c];
    float rs = rsqrtf(bn_var[idx] + 1e-5f);
    float sv = bn_g[idx] * rs;
    coef_s[idx] = sv;
    coef_t[idx] = (b - bn_mean[idx]) * sv + bn_b[idx];
}

// ---------------- GCN edge scatter: agg[dst] += gw[src]*dinv[s]*dinv[d] -----
__global__ void edge_scatter_kernel(const int* __restrict__ src, const int* __restrict__ dst,
                                    const float* __restrict__ gw, const float* __restrict__ dinv,
                                    float* __restrict__ agg)
{
    int idx = blockIdx.x * blockDim.x + threadIdx.x;   // over E*64
    if (idx >= E_EDGES * 64) return;
    int e = idx >> 6;
    int c = (idx & 63) << 2;
    int s = src[e], d = dst[e];
    float w = dinv[s] * dinv[d];
    float4 gv = *reinterpret_cast<const float4*>(&gw[(size_t)s * HID + c]);
    float* base = &agg[(size_t)d * HID + c];
    asm volatile("red.global.add.v4.f32 [%0], {%1, %2, %3, %4};"
                 :: "l"(base), "f"(gv.x * w), "f"(gv.y * w), "f"(gv.z * w), "f"(gv.w * w)
                 : "memory");
}

// ---------------- final: affine(layer4) -> l2 norm -> out_g + pool ----------
__global__ void __launch_bounds__(256) final_kernel(
    const float* __restrict__ agg, const float* __restrict__ s4, const float* __restrict__ t4,
    const int* __restrict__ batch,
    float* __restrict__ out_g, float* __restrict__ out_pool)
{
    __shared__ float sh[16];
    int row = blockIdx.x, c = threadIdx.x;
    float v = agg[(size_t)row * HID + c] * s4[c] + t4[c];
    float ss = block_sum_256(v * v, sh);
    float y = v / fmaxf(sqrtf(ss), 1e-12f);
    out_g[(size_t)row * HID + c] = y;
    atomicAdd(&out_pool[(size_t)batch[row] * HID + c], y);
}

// ---------------- launcher ----------------
extern "C" void kernel_launch(void* const* d_in, const int* in_sizes, int n_in,
                              void* d_out, int out_size)
{
    const float* x       = (const float*)d_in[0];
    const int*   edge    = (const int*)  d_in[1];
    const int*   batch   = (const int*)  d_in[2];
    // d_in[3] = beta (unused)
    const float* fc_W    = (const float*)d_in[4];
    const float* fc_b    = (const float*)d_in[5];
    const float* ln0_g   = (const float*)d_in[6];
    const float* ln0_b   = (const float*)d_in[7];
    const float* Wq      = (const float*)d_in[8];
    const float* bq      = (const float*)d_in[9];
    const float* Wk      = (const float*)d_in[10];
    const float* bk      = (const float*)d_in[11];
    const float* Wv      = (const float*)d_in[12];
    const float* bv      = (const float*)d_in[13];
    const float* ln1_g   = (const float*)d_in[14];
    const float* ln1_b   = (const float*)d_in[15];
    const float* gcn_W0  = (const float*)d_in[16];
    const float* gcn_b0  = (const float*)d_in[17];
    const float* gcn_W   = (const float*)d_in[18];
    const float* gcn_b   = (const float*)d_in[19];
    const float* bn_g    = (const float*)d_in[20];
    const float* bn_b    = (const float*)d_in[21];
    const float* bn_mean = (const float*)d_in[22];
    const float* bn_var  = (const float*)d_in[23];

    const int* src = edge;
    const int* dst = edge + E_EDGES;

    float* out      = (float*)d_out;
    float* out_pool = out;                               // [G, HID]
    float* out_g    = out + (size_t)G_GRP * HID;         // [N, HID]
    float* out_xt   = out_g + (size_t)N_NODES * HID;     // [N, HID]

    float* base = nullptr;
    cudaGetSymbolAddress((void**)&base, d_scratch);
    float* p_h     = base;
    float* p_q     = base + (size_t)1 * NH;
    float* p_k     = base + (size_t)2 * NH;
    float* p_v     = base + (size_t)3 * NH;
    float* p_t     = base + (size_t)4 * NH;
    float* p_aggB  = base + (size_t)5 * NH;
    float* p_aggA  = base + (size_t)6 * NH;
    float* p_kvs   = base + (size_t)7 * NH;
    float* p_kssum = p_kvs + HID * HID;
    float* p_scal  = p_kssum + HID;
    float* p_dinv  = p_scal + 16;
    float* p_cs    = p_dinv + N_NODES;          // coef s [5][256]
    float* p_ct    = p_cs + NUM_GC * HID;       // coef t [5][256]

    const dim3 gg(HID / 128, (N_NODES + 127) / 128);   // (2, 391)
    const int THR = 256;

    // ===== TransConv branch =====
    sgemm128<<<gg, THR>>>(x, fc_W, fc_b, nullptr, nullptr, 0,
                          p_t, nullptr, nullptr, N_NODES, HID, F_IN);
    ln_relu_kernel<<<N_NODES, THR>>>(p_t, ln0_g, ln0_b, p_h);

    sgemm128<<<gg, THR>>>(p_h, Wq, bq, nullptr, nullptr, 0,
                          p_q, nullptr, nullptr, N_NODES, HID, HID);
    sgemm128<<<gg, THR>>>(p_h, Wk, bk, nullptr, nullptr, 0,
                          p_k, nullptr, nullptr, N_NODES, HID, HID);
    sgemm128<<<gg, THR>>>(p_h, Wv, bv, nullptr, nullptr, 0,
                          p_v, nullptr, nullptr, N_NODES, HID, HID);

    zero_kernel<<<(HID * HID + HID + 16 + THR - 1) / THR, THR>>>(p_kvs, HID * HID + HID + 16);
    sumsq_kernel<<<1024, THR>>>((const float4*)p_q, NH / 4, &p_scal[0]);
    colsum_sq_kernel<<<256, THR>>>(p_k, p_kssum, &p_scal[1]);

    {
        const int SPLITS = 64;
        const int rows_per_z = (N_NODES + SPLITS - 1) / SPLITS;
        atb_kernel<<<dim3(HID / 64, HID / 64, SPLITS), THR>>>(p_k, p_v, p_kvs, N_NODES, rows_per_z);
    }
    scale_kvs_kernel<<<(HID * HID + THR - 1) / THR, THR>>>(p_kvs, p_kssum, p_scal);

    sgemm128<<<gg, THR>>>(p_q, p_kvs, nullptr, nullptr, nullptr, 0,
                          p_t, nullptr, nullptr, N_NODES, HID, HID);
    trans_epi_kernel<<<N_NODES, THR>>>(p_q, p_t, p_v, p_h, p_kssum, p_scal,
                                       ln1_g, ln1_b, out_xt);

    // ===== GCN branch =====
    bn_coef_kernel<<<(NUM_GC * HID + THR - 1) / THR, THR>>>(
        gcn_b0, gcn_b, bn_g, bn_b, bn_mean, bn_var, p_cs, p_ct);
    deg_init_kernel<<<(N_NODES + THR - 1) / THR, THR>>>(p_dinv);
    deg_scatter_kernel<<<(E_EDGES + THR - 1) / THR, THR>>>(dst, p_dinv);
    dinv_kernel<<<(N_NODES + THR - 1) / THR, THR>>>(p_dinv);

    const int ELEM4_E = E_EDGES * 64;
    float* agg_cur = p_aggA;
    float* agg_prev = nullptr;

    for (int i = 0; i < NUM_GC; i++) {
        const float* W = (i == 0) ? gcn_W0 : gcn_W + (size_t)(i - 1) * HID * HID;
        const float* Ain = (i == 0) ? x : agg_prev;
        int K = (i == 0) ? F_IN : HID;
        const float* as = (i == 0) ? nullptr : p_cs + (size_t)(i - 1) * HID;
        const float* at = (i == 0) ? nullptr : p_ct + (size_t)(i - 1) * HID;

        // gw = affine(Ain) @ W ; agg_cur = gw * dinv^2 (self loop)
        sgemm128<<<gg, THR>>>(Ain, W, nullptr, as, at, (i == 0) ? 0 : 1,
                              p_t, agg_cur, p_dinv, N_NODES, HID, K);
        edge_scatter_kernel<<<(ELEM4_E + THR - 1) / THR, THR>>>(
            src, dst, p_t, p_dinv, agg_cur);

        agg_prev = agg_cur;
        agg_cur = (agg_cur == p_aggA) ? p_aggB : p_aggA;
    }

    // ===== outputs =====
    zero_kernel<<<(G_GRP * HID + THR - 1) / THR, THR>>>(out_pool, G_GRP * HID);
    final_kernel<<<N_NODES, THR>>>(agg_prev, p_cs + (size_t)(NUM_GC - 1) * HID,
                                   p_ct + (size_t)(NUM_GC - 1) * HID,
                                   batch, out_g, out_pool);
}